// round 1
// baseline (speedup 1.0000x reference)
#include <cuda_runtime.h>
#include <cuda_bf16.h>

#define L_STEPS 256
#define EPSV 1e-12f

__device__ __forceinline__ float stepD(float D, float lam, float beta) {
    float om = fmaxf(1.0f - D, EPSV);
    float lg;
    asm("lg2.approx.f32 %0, %1;" : "=f"(lg) : "f"(om));
    float e = beta * lg;
    float p;
    asm("ex2.approx.f32 %0, %1;" : "=f"(p) : "f"(e));
    // D + lam * (1-D)^beta, clamped to 1.0 (1 - 1e-12 rounds to 1.0f in fp32,
    // matching the float32 reference exactly)
    return fminf(fmaf(lam, p, D), 1.0f);
}

__global__ __launch_bounds__(256) void ductile_kernel(
    const float2* __restrict__ model_out,
    float4* __restrict__ out,
    int B)
{
    int b = blockIdx.x * blockDim.x + threadIdx.x;
    if (b >= B) return;

    float2 mo = model_out[b];
    float lam  = 0.001f * fmaxf(mo.x, 0.0f);
    float beta = fmaf(10.0f, fmaxf(mo.y, 0.0f), 1.0f);

    float D = 0.0f;
    float4* o = out + (size_t)b * (L_STEPS / 4);

    #pragma unroll 4
    for (int c = 0; c < L_STEPS / 4; ++c) {
        float4 v;
        D = stepD(D, lam, beta); v.x = D;
        D = stepD(D, lam, beta); v.y = D;
        D = stepD(D, lam, beta); v.z = D;
        D = stepD(D, lam, beta); v.w = D;
        o[c] = v;
    }
}

extern "C" void kernel_launch(void* const* d_in, const int* in_sizes, int n_in,
                              void* d_out, int out_size)
{
    const float2* model_out = (const float2*)d_in[0];
    float4* out = (float4*)d_out;
    int B = in_sizes[0] / 2;   // model_out is (B, 2) fp32

    int threads = 256;
    int blocks = (B + threads - 1) / threads;
    ductile_kernel<<<blocks, threads>>>(model_out, out, B);
}

// round 3
// speedup vs baseline: 2.5534x; 2.5534x over previous
#include <cuda_runtime.h>
#include <cuda_bf16.h>

#define L_STEPS 256
#define CHUNK   32
#define EPSV    1e-12f

__device__ __forceinline__ float stepD(float D, float lam, float beta) {
    float om = fmaxf(1.0f - D, EPSV);
    float lg;
    asm("lg2.approx.f32 %0, %1;" : "=f"(lg) : "f"(om));
    float e = beta * lg;
    float p;
    asm("ex2.approx.f32 %0, %1;" : "=f"(p) : "f"(e));
    // D + lam*(1-D)^beta, clamped to 1.0 (1-1e-12 rounds to 1.0f in fp32)
    return fminf(fmaf(lam, p, D), 1.0f);
}

__global__ __launch_bounds__(256) void ductile_kernel(
    const float2* __restrict__ model_out,
    float4* __restrict__ out,   // viewed as float4; each row = 64 float4
    int B)
{
    __shared__ float tile[256 * 33];   // stride 33: conflict-free both phases

    const int tid = threadIdx.x;
    const int b0  = blockIdx.x * 256;      // first batch row of this block
    const int b   = b0 + tid;

    float lam = 0.0f, beta = 1.0f;
    if (b < B) {
        float2 mo = model_out[b];
        lam  = 0.001f * fmaxf(mo.x, 0.0f);
        beta = fmaf(10.0f, fmaxf(mo.y, 0.0f), 1.0f);
    }

    float D = 0.0f;
    float4* orow = out + (size_t)b0 * (L_STEPS / 4);

    for (int ch = 0; ch < L_STEPS / CHUNK; ++ch) {
        // ---- compute CHUNK steps, stage into smem (bank (tid+c)%32, no conflict)
        float* my = &tile[tid * 33];
        #pragma unroll
        for (int c = 0; c < CHUNK; ++c) {
            D = stepD(D, lam, beta);
            my[c] = D;
        }
        __syncthreads();

        // ---- transposed, fully-coalesced write-out
        // 256 rows x 32 cols = 2048 float4; 256 threads -> 8 passes.
        // 8-thread groups cover one row's 32 floats = one 128B line.
        #pragma unroll
        for (int p = 0; p < 8; ++p) {
            int idx = p * 256 + tid;
            int r   = idx >> 3;        // row within block (0..255)
            int c4  = idx & 7;         // float4 index within chunk (0..7)
            const float* src = &tile[r * 33 + c4 * 4];
            float4 v;
            v.x = src[0]; v.y = src[1]; v.z = src[2]; v.w = src[3];
            if (b0 + r < B)
                orow[(size_t)r * (L_STEPS / 4) + ch * (CHUNK / 4) + c4] = v;
        }
        __syncthreads();
    }
}

extern "C" void kernel_launch(void* const* d_in, const int* in_sizes, int n_in,
                              void* d_out, int out_size)
{
    const float2* model_out = (const float2*)d_in[0];
    float4* out = (float4*)d_out;
    int B = in_sizes[0] / 2;

    int threads = 256;
    int blocks = (B + threads - 1) / threads;
    ductile_kernel<<<blocks, threads>>>(model_out, out, B);
}